// round 7
// baseline (speedup 1.0000x reference)
#include <cuda_runtime.h>
#include <cuda_bf16.h>
#include <cuda_fp16.h>
#include <math.h>
#include <stdint.h>

#define SEQ  2048
#define EMB  512
#define MTOT 8192

// ---- scratch: static device globals ----
__device__ __nv_bfloat16 g_x [(size_t)MTOT*1024];   // [hi|lo] along K
__device__ __nv_bfloat16 g_wq[(size_t)EMB*1024];
__device__ __nv_bfloat16 g_wk[(size_t)EMB*1024];
__device__ __nv_bfloat16 g_wv[(size_t)EMB*1024];
__device__ __nv_bfloat16 g_wp[(size_t)EMB*1024];
__device__ __nv_bfloat16 g_qc[(size_t)32*SEQ*128];  // [bh][n][hi64|lo64]
__device__ __nv_bfloat16 g_kc[(size_t)32*SEQ*128];  // [bh][n][hi64|lo64]
__device__ __half        g_vf[(size_t)32*SEQ*64];   // [bh][n][64] single fp16
__device__ __nv_bfloat16 g_c [(size_t)MTOT*1024];   // ctx [m][hi512|lo512]

__device__ __forceinline__ uint32_t smem_u32(const void* p) {
    uint32_t a;
    asm("{ .reg .u64 t; cvta.to.shared.u64 t, %1; cvt.u32.u64 %0, t; }" : "=r"(a) : "l"(p));
    return a;
}

#define CP16(d, s) asm volatile("cp.async.cg.shared.global [%0], [%1], 16;" :: "r"(d), "l"(s))
#define CPC()      asm volatile("cp.async.commit_group;" ::: "memory")
#define CPW1()     asm volatile("cp.async.wait_group 1;" ::: "memory")
#define CPW2()     asm volatile("cp.async.wait_group 2;" ::: "memory")

#define LDSM4(r, a) \
    asm volatile("ldmatrix.sync.aligned.m8n8.x4.shared.b16 {%0,%1,%2,%3}, [%4];" \
        : "=r"((r)[0]),"=r"((r)[1]),"=r"((r)[2]),"=r"((r)[3]) : "r"(a))
#define LDSM4T(r, a) \
    asm volatile("ldmatrix.sync.aligned.m8n8.x4.trans.shared.b16 {%0,%1,%2,%3}, [%4];" \
        : "=r"((r)[0]),"=r"((r)[1]),"=r"((r)[2]),"=r"((r)[3]) : "r"(a))

#define MMA(c, a, b0, b1) \
    asm volatile("mma.sync.aligned.m16n8k16.row.col.f32.bf16.bf16.f32 " \
        "{%0,%1,%2,%3},{%4,%5,%6,%7},{%8,%9},{%0,%1,%2,%3};" \
        : "+f"((c)[0]),"+f"((c)[1]),"+f"((c)[2]),"+f"((c)[3]) \
        : "r"((a)[0]),"r"((a)[1]),"r"((a)[2]),"r"((a)[3]),"r"(b0),"r"(b1))
#define MMAH(c, a, b0, b1) \
    asm volatile("mma.sync.aligned.m16n8k16.row.col.f32.f16.f16.f32 " \
        "{%0,%1,%2,%3},{%4,%5,%6,%7},{%8,%9},{%0,%1,%2,%3};" \
        : "+f"((c)[0]),"+f"((c)[1]),"+f"((c)[2]),"+f"((c)[3]) \
        : "r"((a)[0]),"r"((a)[1]),"r"((a)[2]),"r"((a)[3]),"r"(b0),"r"(b1))

__device__ __forceinline__ uint32_t packb(__nv_bfloat16 a, __nv_bfloat16 b) {
    return (uint32_t)__bfloat16_as_ushort(a) | ((uint32_t)__bfloat16_as_ushort(b) << 16);
}
__device__ __forceinline__ uint32_t pack_hi2(float a, float b) {
    return packb(__float2bfloat16(a), __float2bfloat16(b));
}
__device__ __forceinline__ uint32_t pack_lo2(float a, float b) {
    __nv_bfloat16 ha = __float2bfloat16(a), hb = __float2bfloat16(b);
    return packb(__float2bfloat16(a - __bfloat162float(ha)),
                 __float2bfloat16(b - __bfloat162float(hb)));
}
__device__ __forceinline__ uint32_t packh(float a, float b) {
    __half2 t = __floats2half2_rn(a, b);
    return *reinterpret_cast<uint32_t*>(&t);
}

// ---------------- fp32 -> [hi|lo] bf16, all 5 tensors in one launch ----------------
__global__ void conv_all(
    const float* __restrict__ x,  const float* __restrict__ Wq,
    const float* __restrict__ Wk, const float* __restrict__ Wv,
    const float* __restrict__ Wp)
{
    const float* src;
    __nv_bfloat16* dst;
    int bid = blockIdx.x;
    if (bid < 4096) { src = x; dst = g_x; }
    else {
        int w = (bid - 4096) >> 8;
        bid = (bid - 4096) & 255;
        switch (w) {
            case 0: src = Wq; dst = g_wq; break;
            case 1: src = Wk; dst = g_wk; break;
            case 2: src = Wv; dst = g_wv; break;
            default: src = Wp; dst = g_wp; break;
        }
    }
    int i4 = ((blockIdx.x < 4096 ? blockIdx.x : bid) * 256 + threadIdx.x) * 4;
    float4 v = *(const float4*)(src + i4);
    int m = i4 >> 9, e = i4 & 511;
    *(uint2*)(dst + (size_t)m * 1024 + e) =
        make_uint2(pack_hi2(v.x, v.y), pack_hi2(v.z, v.w));
    *(uint2*)(dst + (size_t)m * 1024 + 512 + e) =
        make_uint2(pack_lo2(v.x, v.y), pack_lo2(v.z, v.w));
}

// ---------------- GEMM: 128x128 tile, K segments of 64 ----------------
__device__ __forceinline__ void gemm_ld_stage(
    const __nv_bfloat16* __restrict__ A, const __nv_bfloat16* __restrict__ B,
    int m0, int bn0, int chunk, uint32_t sstage, int tid)
{
    int seg = chunk >> 3, i = chunk & 7;
    int kA = ((seg == 1) ? 512 : 0) + i * 64;   // A segs: hi, lo, hi
    int kB = ((seg == 2) ? 512 : 0) + i * 64;   // B segs: hi, hi, lo
    #pragma unroll
    for (int j = 0; j < 4; j++) {
        int idx = tid + j * 256;
        int r = idx >> 3, c = idx & 7;
        uint32_t off = r * 128 + ((c ^ (r & 7)) << 4);
        CP16(sstage + off,         A + (size_t)(m0 + r) * 1024 + kA + c * 8);
        CP16(sstage + 16384 + off, B + (size_t)(bn0 + r) * 1024 + kB + c * 8);
    }
}

#define GEMM_SMEM 98304

__global__ void __launch_bounds__(256, 2) gemm_kernel(
    int mode, const float* __restrict__ bq, const float* __restrict__ bk,
    const float* __restrict__ bv, float* __restrict__ out)
{
    extern __shared__ __align__(16) char sm[];
    uint32_t sb = smem_u32(sm);
    const int tid = threadIdx.x, lane = tid & 31, wid = tid >> 5;
    const int wm = wid >> 2, wn = wid & 3;
    const int m0 = blockIdx.y * 128, c0 = blockIdx.x * 128;

    const __nv_bfloat16 *A, *B;
    const float* bias;
    int w = 0, bn0 = c0;
    if (mode == 0) {
        w = c0 >> 9; bn0 = c0 & 511;
        A = g_x;
        B = (w == 0) ? g_wq : (w == 1) ? g_wk : g_wv;
        bias = (w == 0) ? bq : (w == 1) ? bk : bv;
    } else {
        A = g_c; B = g_wp; bias = bq;
    }
    // V columns need only fp16-level precision downstream -> 2-term (16 chunks)
    const int NC = (mode == 0 && w == 2) ? 16 : 24;

    float acc[4][4][4];
    #pragma unroll
    for (int i = 0; i < 4; i++)
        #pragma unroll
        for (int j = 0; j < 4; j++)
            #pragma unroll
            for (int k = 0; k < 4; k++) acc[i][j][k] = 0.f;

    gemm_ld_stage(A, B, m0, bn0, 0, sb, tid);          CPC();
    gemm_ld_stage(A, B, m0, bn0, 1, sb + 32768, tid);  CPC();

    for (int c = 0; c < NC; c++) {
        if (c + 2 < NC) gemm_ld_stage(A, B, m0, bn0, c + 2, sb + ((c + 2) % 3) * 32768, tid);
        CPC();
        CPW2();
        __syncthreads();
        uint32_t As = sb + (c % 3) * 32768;
        uint32_t Bs = As + 16384;
        #pragma unroll
        for (int ks = 0; ks < 4; ks++) {
            uint32_t a[4][4];
            #pragma unroll
            for (int mi = 0; mi < 4; mi++) {
                int r = wm * 64 + mi * 16 + (lane & 15);
                int c16 = 2 * ks + (lane >> 4);
                LDSM4(a[mi], As + r * 128 + ((c16 ^ (r & 7)) << 4));
            }
            uint32_t bf[2][4];
            #pragma unroll
            for (int bi = 0; bi < 2; bi++) {
                int n = wn * 32 + bi * 16 + (lane & 7) + ((lane >> 4) << 3);
                int c16 = 2 * ks + ((lane >> 3) & 1);
                LDSM4(bf[bi], Bs + n * 128 + ((c16 ^ (n & 7)) << 4));
            }
            #pragma unroll
            for (int mi = 0; mi < 4; mi++)
                #pragma unroll
                for (int ni = 0; ni < 4; ni++)
                    MMA(acc[mi][ni], a[mi], bf[ni >> 1][(ni & 1) * 2], bf[ni >> 1][(ni & 1) * 2 + 1]);
        }
        __syncthreads();
    }

    // ---- epilogue ----
    #pragma unroll
    for (int mi = 0; mi < 4; mi++) {
        #pragma unroll
        for (int ni = 0; ni < 4; ni++) {
            int r0 = m0 + wm * 64 + mi * 16 + (lane >> 2);
            int col = bn0 + wn * 32 + ni * 8 + 2 * (lane & 3);
            float v00 = acc[mi][ni][0] + bias[col];
            float v01 = acc[mi][ni][1] + bias[col + 1];
            float v10 = acc[mi][ni][2] + bias[col];
            float v11 = acc[mi][ni][3] + bias[col + 1];
            if (mode == 1) {
                *(float2*)(out + (size_t)r0 * 512 + col)       = make_float2(v00, v01);
                *(float2*)(out + (size_t)(r0 + 8) * 512 + col) = make_float2(v10, v11);
            } else {
                int h = col >> 6, d = col & 63;
                #pragma unroll
                for (int rr = 0; rr < 2; rr++) {
                    int r = r0 + rr * 8;
                    float va = rr ? v10 : v00, vb = rr ? v11 : v01;
                    int bh = (r >> 11) * 8 + h;
                    int n = r & 2047;
                    if (w < 2) {
                        __nv_bfloat16* dq = (w == 0) ? g_qc : g_kc;
                        size_t base = ((size_t)bh * SEQ + n) * 128 + d;
                        *(uint32_t*)(dq + base)      = pack_hi2(va, vb);
                        *(uint32_t*)(dq + base + 64) = pack_lo2(va, vb);
                    } else {
                        size_t base = ((size_t)bh * SEQ + n) * 64 + d;
                        *(uint32_t*)(g_vf + base) = packh(va, vb);
                    }
                }
            }
        }
    }
}

// ---------------- attention: 512 threads, 16 warps ----------------
// warp = (row-group rw 0..7) x (key-half kw 0..1): 16 q-rows x 64 keys
// smem: Qh 0 | Ql 16K | stage s @ 32K + 48K*s: Kh 0 | Kl 16K | V 32K
// end-of-kernel reduction buffer reuses stage0 (32KB oc + 512B ls)
#define ATT_STAGE 49152
#define ATT_SMEM  (32768 + 2 * ATT_STAGE)

__device__ __forceinline__ void attn_ld_kv(
    const __nv_bfloat16* __restrict__ kcb, const __half* __restrict__ vfb,
    int t, uint32_t sstage, int tid)
{
    int k0 = t * 128;
    #pragma unroll
    for (int j = 0; j < 4; j++) {
        int idx = tid + j * 512;
        int r = idx >> 4, c16 = idx & 15;
        int part = c16 >> 3, cc = c16 & 7;
        CP16(sstage + part * 16384 + r * 128 + ((cc ^ (r & 7)) << 4),
             kcb + (size_t)(k0 + r) * 128 + c16 * 8);
    }
    #pragma unroll
    for (int j = 0; j < 2; j++) {
        int idx = tid + j * 512;
        int r = idx >> 3, c16 = idx & 7;
        uint32_t off = r * 128 + ((c16 ^ (r & 7)) << 4);
        CP16(sstage + 32768 + off, vfb + (size_t)(k0 + r) * 64 + c16 * 8);
    }
}

__global__ void __launch_bounds__(512, 1) attn_kernel()
{
    extern __shared__ __align__(16) char sm[];
    uint32_t sb = smem_u32(sm);
    const int tid = threadIdx.x, lane = tid & 31, wid = tid >> 5;
    const int rw = wid & 7, kw = wid >> 3;
    const int kb = kw * 64;
    const int q0 = blockIdx.x * 128;
    const int bh = blockIdx.y, b = bh >> 3, h = bh & 7;

    const __nv_bfloat16* qcb = g_qc + (size_t)bh * SEQ * 128;
    const __nv_bfloat16* kcb = g_kc + (size_t)bh * SEQ * 128;
    const __half* vfb = g_vf + (size_t)bh * SEQ * 64;

    // Q -> smem (hi/lo), grouped with stage-0 K/V
    #pragma unroll
    for (int j = 0; j < 4; j++) {
        int idx = tid + j * 512;
        int r = idx >> 4, c16 = idx & 15;
        int part = c16 >> 3, cc = c16 & 7;
        CP16(sb + part * 16384 + r * 128 + ((cc ^ (r & 7)) << 4),
             qcb + (size_t)(q0 + r) * 128 + c16 * 8);
    }
    attn_ld_kv(kcb, vfb, 0, sb + 32768, tid);
    CPC();

    float oc[8][4];
    #pragma unroll
    for (int i = 0; i < 8; i++)
        #pragma unroll
        for (int j = 0; j < 4; j++) oc[i][j] = 0.f;
    float ls0 = 0.f, ls1 = 0.f;
    const float psc = 1.0f / 4096.0f;

    for (int t = 0; t < 16; t++) {
        if (t + 1 < 16) attn_ld_kv(kcb, vfb, t + 1, sb + 32768 + ((t + 1) & 1) * ATT_STAGE, tid);
        CPC();
        CPW1();
        __syncthreads();

        uint32_t Kbase = sb + 32768 + (t & 1) * ATT_STAGE;
        float sc[8][4];
        #pragma unroll
        for (int i = 0; i < 8; i++)
            #pragma unroll
            for (int j = 0; j < 4; j++) sc[i][j] = 0.f;

        // S (this warp: 16 rows x its 64-key half) = Qh*Kh + Ql*Kh + Qh*Kl
        #pragma unroll
        for (int ksx = 0; ksx < 4; ksx++) {
            uint32_t ah4[4], al4[4];
            int r = 16 * rw + (lane & 15);
            int c16 = 2 * ksx + (lane >> 4);
            uint32_t aoff = r * 128 + ((c16 ^ (r & 7)) << 4);
            LDSM4(ah4, sb + aoff);
            LDSM4(al4, sb + 16384 + aoff);
            #pragma unroll
            for (int bi = 0; bi < 4; bi++) {
                int n = kb + bi * 16 + (lane & 7) + ((lane >> 4) << 3);
                int c16b = 2 * ksx + ((lane >> 3) & 1);
                uint32_t boff = n * 128 + ((c16b ^ (n & 7)) << 4);
                uint32_t bh4[4], bl4[4];
                LDSM4(bh4, Kbase + boff);
                LDSM4(bl4, Kbase + 16384 + boff);
                MMA(sc[2 * bi],     ah4, bh4[0], bh4[1]);
                MMA(sc[2 * bi],     al4, bh4[0], bh4[1]);
                MMA(sc[2 * bi],     ah4, bl4[0], bl4[1]);
                MMA(sc[2 * bi + 1], ah4, bh4[2], bh4[3]);
                MMA(sc[2 * bi + 1], al4, bh4[2], bh4[3]);
                MMA(sc[2 * bi + 1], ah4, bl4[2], bl4[3]);
            }
        }

        // softmax (no max subtraction; partial row sums over this key half)
        #pragma unroll
        for (int j = 0; j < 8; j++) {
            float p0 = __expf(sc[j][0]), p1 = __expf(sc[j][1]);
            float p2 = __expf(sc[j][2]), p3 = __expf(sc[j][3]);
            sc[j][0] = p0; sc[j][1] = p1; sc[j][2] = p2; sc[j][3] = p3;
            ls0 += p0 + p1; ls1 += p2 + p3;
        }

        // O += P*V over this warp's 64 keys (single fp16 P, scaled 2^-12)
        uint32_t V_s = Kbase + 32768;
        #pragma unroll
        for (int k = 0; k < 4; k++) {
            uint32_t ah4[4];
            ah4[0] = packh(sc[2*k][0] * psc,   sc[2*k][1] * psc);
            ah4[1] = packh(sc[2*k][2] * psc,   sc[2*k][3] * psc);
            ah4[2] = packh(sc[2*k+1][0] * psc, sc[2*k+1][1] * psc);
            ah4[3] = packh(sc[2*k+1][2] * psc, sc[2*k+1][3] * psc);
            #pragma unroll
            for (int vi = 0; vi < 4; vi++) {
                uint32_t bv4[4];
                int row = kb + 16 * k + (lane & 15);
                int c16 = 2 * vi + (lane >> 4);
                LDSM4T(bv4, V_s + row * 128 + ((c16 ^ (row & 7)) << 4));
                MMAH(oc[2*vi],   ah4, bv4[0], bv4[1]);
                MMAH(oc[2*vi+1], ah4, bv4[2], bv4[3]);
            }
        }
        __syncthreads();
    }

    // reduce partial row sums across the 4 lanes of each row quad
    ls0 += __shfl_xor_sync(0xffffffffu, ls0, 1);
    ls0 += __shfl_xor_sync(0xffffffffu, ls0, 2);
    ls1 += __shfl_xor_sync(0xffffffffu, ls1, 1);
    ls1 += __shfl_xor_sync(0xffffffffu, ls1, 2);

    // cross-key-half reduction: kw=1 warps publish, kw=0 warps combine
    __syncthreads();
    float* red  = (float*)(sm + 32768);          // [8 warps][16 rows][64 cols]
    float* redl = (float*)(sm + 32768 + 32768);  // [8 warps][16 rows]
    if (kw == 1) {
        float* po = red + rw * 1024;
        #pragma unroll
        for (int ni = 0; ni < 8; ni++)
            #pragma unroll
            for (int j = 0; j < 4; j++) {
                int rl = (lane >> 2) + ((j >> 1) << 3);
                int col = ni * 8 + 2 * (lane & 3) + (j & 1);
                po[rl * 64 + col] = oc[ni][j];
            }
        if ((lane & 3) == 0) {
            redl[rw * 16 + (lane >> 2)]     = ls0;
            redl[rw * 16 + 8 + (lane >> 2)] = ls1;
        }
    }
    __syncthreads();
    if (kw == 0) {
        float* po = red + rw * 1024;
        #pragma unroll
        for (int ni = 0; ni < 8; ni++)
            #pragma unroll
            for (int j = 0; j < 4; j++) {
                int rl = (lane >> 2) + ((j >> 1) << 3);
                int col = ni * 8 + 2 * (lane & 3) + (j & 1);
                oc[ni][j] += po[rl * 64 + col];
            }
        ls0 += redl[rw * 16 + (lane >> 2)];
        ls1 += redl[rw * 16 + 8 + (lane >> 2)];

        const float kInv = 0.04419417382415922f;  // 1/sqrt(512)
        float inv0 = 4096.0f * kInv / ls0, inv1 = 4096.0f * kInv / ls1;

        int r0l = 16 * rw + (lane >> 2);
        size_t m0r = (size_t)b * SEQ + q0 + r0l;
        __nv_bfloat16* c0p = g_c + m0r * 1024 + h * 64;
        __nv_bfloat16* c1p = g_c + (m0r + 8) * 1024 + h * 64;
        #pragma unroll
        for (int ni = 0; ni < 8; ni++) {
            int d = 8 * ni + 2 * (lane & 3);
            float v00 = oc[ni][0] * inv0, v01 = oc[ni][1] * inv0;
            float v10 = oc[ni][2] * inv1, v11 = oc[ni][3] * inv1;
            *(uint32_t*)(c0p + d)       = pack_hi2(v00, v01);
            *(uint32_t*)(c0p + 512 + d) = pack_lo2(v00, v01);
            *(uint32_t*)(c1p + d)       = pack_hi2(v10, v11);
            *(uint32_t*)(c1p + 512 + d) = pack_lo2(v10, v11);
        }
    }
}

// ---------------------------------------------------------------------------
extern "C" void kernel_launch(void* const* d_in, const int* in_sizes, int n_in,
                              void* d_out, int out_size)
{
    const float* x  = (const float*)d_in[0];
    const float* Wq = (const float*)d_in[1];
    const float* bq = (const float*)d_in[2];
    const float* Wk = (const float*)d_in[3];
    const float* bk = (const float*)d_in[4];
    const float* Wv = (const float*)d_in[5];
    const float* bv = (const float*)d_in[6];
    const float* Wp = (const float*)d_in[7];
    const float* bp = (const float*)d_in[8];
    float* out = (float*)d_out;

    cudaFuncSetAttribute(gemm_kernel, cudaFuncAttributeMaxDynamicSharedMemorySize, GEMM_SMEM);
    cudaFuncSetAttribute(attn_kernel, cudaFuncAttributeMaxDynamicSharedMemorySize, ATT_SMEM);

    conv_all<<<4096 + 4 * 256, 256>>>(x, Wq, Wk, Wv, Wp);

    gemm_kernel<<<dim3(12, 64), 256, GEMM_SMEM>>>(0, bq, bk, bv, nullptr);
    attn_kernel<<<dim3(16, 32), 512, ATT_SMEM>>>();
    gemm_kernel<<<dim3(4, 64), 256, GEMM_SMEM>>>(1, bp, nullptr, nullptr, out);
}

// round 8
// speedup vs baseline: 1.1771x; 1.1771x over previous
#include <cuda_runtime.h>
#include <cuda_bf16.h>
#include <cuda_fp16.h>
#include <math.h>
#include <stdint.h>

#define SEQ  2048
#define EMB  512
#define MTOT 8192

// ---- scratch: static device globals ----
__device__ __nv_bfloat16 g_x [(size_t)MTOT*1024];   // [hi|lo] along K
__device__ __nv_bfloat16 g_wq[(size_t)EMB*1024];
__device__ __nv_bfloat16 g_wk[(size_t)EMB*1024];
__device__ __nv_bfloat16 g_wv[(size_t)EMB*1024];
__device__ __nv_bfloat16 g_wp[(size_t)EMB*1024];
__device__ __half        g_qh2[(size_t)32*SEQ*64];  // [bh][n][64] fp16 hi
__device__ __half        g_ql2[(size_t)32*SEQ*64];  // [bh][n][64] fp16 lo
__device__ __half        g_kf [(size_t)32*SEQ*64];  // [bh][n][64] single fp16
__device__ __half        g_vf [(size_t)32*SEQ*64];  // [bh][n][64] single fp16
__device__ __nv_bfloat16 g_c [(size_t)MTOT*1024];   // ctx [m][hi512|lo512]

__device__ __forceinline__ uint32_t smem_u32(const void* p) {
    uint32_t a;
    asm("{ .reg .u64 t; cvta.to.shared.u64 t, %1; cvt.u32.u64 %0, t; }" : "=r"(a) : "l"(p));
    return a;
}

#define CP16(d, s) asm volatile("cp.async.cg.shared.global [%0], [%1], 16;" :: "r"(d), "l"(s))
#define CPC()      asm volatile("cp.async.commit_group;" ::: "memory")
#define CPW1()     asm volatile("cp.async.wait_group 1;" ::: "memory")
#define CPW2()     asm volatile("cp.async.wait_group 2;" ::: "memory")

#define LDSM4(r, a) \
    asm volatile("ldmatrix.sync.aligned.m8n8.x4.shared.b16 {%0,%1,%2,%3}, [%4];" \
        : "=r"((r)[0]),"=r"((r)[1]),"=r"((r)[2]),"=r"((r)[3]) : "r"(a))
#define LDSM4T(r, a) \
    asm volatile("ldmatrix.sync.aligned.m8n8.x4.trans.shared.b16 {%0,%1,%2,%3}, [%4];" \
        : "=r"((r)[0]),"=r"((r)[1]),"=r"((r)[2]),"=r"((r)[3]) : "r"(a))

#define MMA(c, a, b0, b1) \
    asm volatile("mma.sync.aligned.m16n8k16.row.col.f32.bf16.bf16.f32 " \
        "{%0,%1,%2,%3},{%4,%5,%6,%7},{%8,%9},{%0,%1,%2,%3};" \
        : "+f"((c)[0]),"+f"((c)[1]),"+f"((c)[2]),"+f"((c)[3]) \
        : "r"((a)[0]),"r"((a)[1]),"r"((a)[2]),"r"((a)[3]),"r"(b0),"r"(b1))
#define MMAH(c, a, b0, b1) \
    asm volatile("mma.sync.aligned.m16n8k16.row.col.f32.f16.f16.f32 " \
        "{%0,%1,%2,%3},{%4,%5,%6,%7},{%8,%9},{%0,%1,%2,%3};" \
        : "+f"((c)[0]),"+f"((c)[1]),"+f"((c)[2]),"+f"((c)[3]) \
        : "r"((a)[0]),"r"((a)[1]),"r"((a)[2]),"r"((a)[3]),"r"(b0),"r"(b1))

__device__ __forceinline__ uint32_t packb(__nv_bfloat16 a, __nv_bfloat16 b) {
    return (uint32_t)__bfloat16_as_ushort(a) | ((uint32_t)__bfloat16_as_ushort(b) << 16);
}
__device__ __forceinline__ uint32_t pack_hi2(float a, float b) {
    return packb(__float2bfloat16(a), __float2bfloat16(b));
}
__device__ __forceinline__ uint32_t pack_lo2(float a, float b) {
    __nv_bfloat16 ha = __float2bfloat16(a), hb = __float2bfloat16(b);
    return packb(__float2bfloat16(a - __bfloat162float(ha)),
                 __float2bfloat16(b - __bfloat162float(hb)));
}
__device__ __forceinline__ uint32_t packh(float a, float b) {
    __half2 t = __floats2half2_rn(a, b);
    return *reinterpret_cast<uint32_t*>(&t);
}
__device__ __forceinline__ uint32_t packh_lo(float a, float b) {
    __half ha = __float2half_rn(a), hb = __float2half_rn(b);
    return packh(a - __half2float(ha), b - __half2float(hb));
}

// ---------------- fp32 -> [hi|lo] bf16, all 5 tensors in one launch ----------------
__global__ void conv_all(
    const float* __restrict__ x,  const float* __restrict__ Wq,
    const float* __restrict__ Wk, const float* __restrict__ Wv,
    const float* __restrict__ Wp)
{
    const float* src;
    __nv_bfloat16* dst;
    int bid = blockIdx.x;
    if (bid < 4096) { src = x; dst = g_x; }
    else {
        int w = (bid - 4096) >> 8;
        bid = (bid - 4096) & 255;
        switch (w) {
            case 0: src = Wq; dst = g_wq; break;
            case 1: src = Wk; dst = g_wk; break;
            case 2: src = Wv; dst = g_wv; break;
            default: src = Wp; dst = g_wp; break;
        }
    }
    int i4 = ((blockIdx.x < 4096 ? blockIdx.x : bid) * 256 + threadIdx.x) * 4;
    float4 v = *(const float4*)(src + i4);
    int m = i4 >> 9, e = i4 & 511;
    *(uint2*)(dst + (size_t)m * 1024 + e) =
        make_uint2(pack_hi2(v.x, v.y), pack_hi2(v.z, v.w));
    *(uint2*)(dst + (size_t)m * 1024 + 512 + e) =
        make_uint2(pack_lo2(v.x, v.y), pack_lo2(v.z, v.w));
}

// ---------------- GEMM: 128x128 tile, K segments of 64 ----------------
__device__ __forceinline__ void gemm_ld_stage(
    const __nv_bfloat16* __restrict__ A, const __nv_bfloat16* __restrict__ B,
    int m0, int bn0, int chunk, uint32_t sstage, int tid)
{
    int seg = chunk >> 3, i = chunk & 7;
    int kA = ((seg == 1) ? 512 : 0) + i * 64;   // A segs: hi, lo, hi
    int kB = ((seg == 2) ? 512 : 0) + i * 64;   // B segs: hi, hi, lo
    #pragma unroll
    for (int j = 0; j < 4; j++) {
        int idx = tid + j * 256;
        int r = idx >> 3, c = idx & 7;
        uint32_t off = r * 128 + ((c ^ (r & 7)) << 4);
        CP16(sstage + off,         A + (size_t)(m0 + r) * 1024 + kA + c * 8);
        CP16(sstage + 16384 + off, B + (size_t)(bn0 + r) * 1024 + kB + c * 8);
    }
}

#define GEMM_SMEM 98304

__global__ void __launch_bounds__(256, 2) gemm_kernel(
    int mode, const float* __restrict__ bq, const float* __restrict__ bk,
    const float* __restrict__ bv, float* __restrict__ out)
{
    extern __shared__ __align__(16) char sm[];
    uint32_t sb = smem_u32(sm);
    const int tid = threadIdx.x, lane = tid & 31, wid = tid >> 5;
    const int wm = wid >> 2, wn = wid & 3;
    const int m0 = blockIdx.y * 128, c0 = blockIdx.x * 128;

    const __nv_bfloat16 *A, *B;
    const float* bias;
    int w = 0, bn0 = c0;
    if (mode == 0) {
        w = c0 >> 9; bn0 = c0 & 511;
        A = g_x;
        B = (w == 0) ? g_wq : (w == 1) ? g_wk : g_wv;
        bias = (w == 0) ? bq : (w == 1) ? bk : bv;
    } else {
        A = g_c; B = g_wp; bias = bq;
    }
    // V columns need only fp16-level precision downstream -> 2-term (16 chunks)
    const int NC = (mode == 0 && w == 2) ? 16 : 24;

    float acc[4][4][4];
    #pragma unroll
    for (int i = 0; i < 4; i++)
        #pragma unroll
        for (int j = 0; j < 4; j++)
            #pragma unroll
            for (int k = 0; k < 4; k++) acc[i][j][k] = 0.f;

    gemm_ld_stage(A, B, m0, bn0, 0, sb, tid);          CPC();
    gemm_ld_stage(A, B, m0, bn0, 1, sb + 32768, tid);  CPC();

    for (int c = 0; c < NC; c++) {
        if (c + 2 < NC) gemm_ld_stage(A, B, m0, bn0, c + 2, sb + ((c + 2) % 3) * 32768, tid);
        CPC();
        CPW2();
        __syncthreads();
        uint32_t As = sb + (c % 3) * 32768;
        uint32_t Bs = As + 16384;
        #pragma unroll
        for (int ks = 0; ks < 4; ks++) {
            uint32_t a[4][4];
            #pragma unroll
            for (int mi = 0; mi < 4; mi++) {
                int r = wm * 64 + mi * 16 + (lane & 15);
                int c16 = 2 * ks + (lane >> 4);
                LDSM4(a[mi], As + r * 128 + ((c16 ^ (r & 7)) << 4));
            }
            uint32_t bf[2][4];
            #pragma unroll
            for (int bi = 0; bi < 2; bi++) {
                int n = wn * 32 + bi * 16 + (lane & 7) + ((lane >> 4) << 3);
                int c16 = 2 * ks + ((lane >> 3) & 1);
                LDSM4(bf[bi], Bs + n * 128 + ((c16 ^ (n & 7)) << 4));
            }
            #pragma unroll
            for (int mi = 0; mi < 4; mi++)
                #pragma unroll
                for (int ni = 0; ni < 4; ni++)
                    MMA(acc[mi][ni], a[mi], bf[ni >> 1][(ni & 1) * 2], bf[ni >> 1][(ni & 1) * 2 + 1]);
        }
        __syncthreads();
    }

    // ---- epilogue ----
    #pragma unroll
    for (int mi = 0; mi < 4; mi++) {
        #pragma unroll
        for (int ni = 0; ni < 4; ni++) {
            int r0 = m0 + wm * 64 + mi * 16 + (lane >> 2);
            int col = bn0 + wn * 32 + ni * 8 + 2 * (lane & 3);
            float v00 = acc[mi][ni][0] + bias[col];
            float v01 = acc[mi][ni][1] + bias[col + 1];
            float v10 = acc[mi][ni][2] + bias[col];
            float v11 = acc[mi][ni][3] + bias[col + 1];
            if (mode == 1) {
                *(float2*)(out + (size_t)r0 * 512 + col)       = make_float2(v00, v01);
                *(float2*)(out + (size_t)(r0 + 8) * 512 + col) = make_float2(v10, v11);
            } else {
                int h = col >> 6, d = col & 63;
                #pragma unroll
                for (int rr = 0; rr < 2; rr++) {
                    int r = r0 + rr * 8;
                    float va = rr ? v10 : v00, vb = rr ? v11 : v01;
                    int bh = (r >> 11) * 8 + h;
                    int n = r & 2047;
                    size_t base = ((size_t)bh * SEQ + n) * 64 + d;
                    if (w == 0) {
                        *(uint32_t*)(g_qh2 + base) = packh(va, vb);
                        *(uint32_t*)(g_ql2 + base) = packh_lo(va, vb);
                    } else if (w == 1) {
                        *(uint32_t*)(g_kf + base) = packh(va, vb);
                    } else {
                        *(uint32_t*)(g_vf + base) = packh(va, vb);
                    }
                }
            }
        }
    }
}

// ---------------- attention: 256 threads, 8 warps, 2 CTAs/SM ----------------
// warp = 16 q-rows x full 128 keys (processed in two 64-key halves)
// smem: Qh 0 | Ql 16K | stage s @ 32K + 32K*s: K 0 | V 16K
#define ATT_STAGE 32768
#define ATT_SMEM  (32768 + 2 * ATT_STAGE)

__device__ __forceinline__ void attn_ld_kv(
    const __half* __restrict__ kfb, const __half* __restrict__ vfb,
    int t, uint32_t sstage, int tid)
{
    int k0 = t * 128;
    #pragma unroll
    for (int j = 0; j < 4; j++) {
        int idx = tid + j * 256;
        int r = idx >> 3, c16 = idx & 7;
        uint32_t off = r * 128 + ((c16 ^ (r & 7)) << 4);
        CP16(sstage + off,         kfb + (size_t)(k0 + r) * 64 + c16 * 8);
        CP16(sstage + 16384 + off, vfb + (size_t)(k0 + r) * 64 + c16 * 8);
    }
}

__global__ void __launch_bounds__(256, 2) attn_kernel()
{
    extern __shared__ __align__(16) char sm[];
    uint32_t sb = smem_u32(sm);
    const int tid = threadIdx.x, lane = tid & 31, wid = tid >> 5;
    const int q0 = blockIdx.x * 128;
    const int bh = blockIdx.y, b = bh >> 3, h = bh & 7;

    const __half* qhb = g_qh2 + (size_t)bh * SEQ * 64;
    const __half* qlb = g_ql2 + (size_t)bh * SEQ * 64;
    const __half* kfb = g_kf + (size_t)bh * SEQ * 64;
    const __half* vfb = g_vf + (size_t)bh * SEQ * 64;

    // Q hi/lo -> smem, grouped with stage-0 K/V
    #pragma unroll
    for (int j = 0; j < 4; j++) {
        int idx = tid + j * 256;
        int r = idx >> 3, c16 = idx & 7;
        uint32_t off = r * 128 + ((c16 ^ (r & 7)) << 4);
        CP16(sb + off,         qhb + (size_t)(q0 + r) * 64 + c16 * 8);
        CP16(sb + 16384 + off, qlb + (size_t)(q0 + r) * 64 + c16 * 8);
    }
    attn_ld_kv(kfb, vfb, 0, sb + 32768, tid);
    CPC();

    float oc[8][4];
    #pragma unroll
    for (int i = 0; i < 8; i++)
        #pragma unroll
        for (int j = 0; j < 4; j++) oc[i][j] = 0.f;
    float ls0 = 0.f, ls1 = 0.f;
    const float psc = 1.0f / 4096.0f;

    for (int t = 0; t < 16; t++) {
        if (t + 1 < 16) attn_ld_kv(kfb, vfb, t + 1, sb + 32768 + ((t + 1) & 1) * ATT_STAGE, tid);
        CPC();
        CPW1();
        __syncthreads();

        uint32_t Kbase = sb + 32768 + (t & 1) * ATT_STAGE;
        uint32_t V_s = Kbase + 16384;

        #pragma unroll
        for (int half = 0; half < 2; half++) {
            const int kb = half * 64;
            float sc[8][4];
            #pragma unroll
            for (int i = 0; i < 8; i++)
                #pragma unroll
                for (int j = 0; j < 4; j++) sc[i][j] = 0.f;

            // S (16 rows x 64 keys) = (Qh + Ql) * K   (fp16 2-term)
            #pragma unroll
            for (int ksx = 0; ksx < 4; ksx++) {
                uint32_t ah4[4], al4[4];
                int r = 16 * wid + (lane & 15);
                int c16 = 2 * ksx + (lane >> 4);
                uint32_t aoff = r * 128 + ((c16 ^ (r & 7)) << 4);
                LDSM4(ah4, sb + aoff);
                LDSM4(al4, sb + 16384 + aoff);
                #pragma unroll
                for (int bi = 0; bi < 4; bi++) {
                    int n = kb + bi * 16 + (lane & 7) + ((lane >> 4) << 3);
                    int c16b = 2 * ksx + ((lane >> 3) & 1);
                    uint32_t bk4[4];
                    LDSM4(bk4, Kbase + n * 128 + ((c16b ^ (n & 7)) << 4));
                    MMAH(sc[2 * bi],     ah4, bk4[0], bk4[1]);
                    MMAH(sc[2 * bi],     al4, bk4[0], bk4[1]);
                    MMAH(sc[2 * bi + 1], ah4, bk4[2], bk4[3]);
                    MMAH(sc[2 * bi + 1], al4, bk4[2], bk4[3]);
                }
            }

            // softmax (no max subtraction; partial sums over this half)
            #pragma unroll
            for (int j = 0; j < 8; j++) {
                float p0 = __expf(sc[j][0]), p1 = __expf(sc[j][1]);
                float p2 = __expf(sc[j][2]), p3 = __expf(sc[j][3]);
                sc[j][0] = p0; sc[j][1] = p1; sc[j][2] = p2; sc[j][3] = p3;
                ls0 += p0 + p1; ls1 += p2 + p3;
            }

            // O += P*V over these 64 keys (single fp16 P, scaled 2^-12)
            #pragma unroll
            for (int k = 0; k < 4; k++) {
                uint32_t ah4[4];
                ah4[0] = packh(sc[2*k][0] * psc,   sc[2*k][1] * psc);
                ah4[1] = packh(sc[2*k][2] * psc,   sc[2*k][3] * psc);
                ah4[2] = packh(sc[2*k+1][0] * psc, sc[2*k+1][1] * psc);
                ah4[3] = packh(sc[2*k+1][2] * psc, sc[2*k+1][3] * psc);
                #pragma unroll
                for (int vi = 0; vi < 4; vi++) {
                    uint32_t bv4[4];
                    int row = kb + 16 * k + (lane & 15);
                    int c16 = 2 * vi + (lane >> 4);
                    LDSM4T(bv4, V_s + row * 128 + ((c16 ^ (row & 7)) << 4));
                    MMAH(oc[2*vi],   ah4, bv4[0], bv4[1]);
                    MMAH(oc[2*vi+1], ah4, bv4[2], bv4[3]);
                }
            }
        }
        __syncthreads();
    }

    // reduce partial row sums across the 4 lanes sharing a row
    ls0 += __shfl_xor_sync(0xffffffffu, ls0, 1);
    ls0 += __shfl_xor_sync(0xffffffffu, ls0, 2);
    ls1 += __shfl_xor_sync(0xffffffffu, ls1, 1);
    ls1 += __shfl_xor_sync(0xffffffffu, ls1, 2);
    const float kInv = 0.04419417382415922f;  // 1/sqrt(512)
    float inv0 = 4096.0f * kInv / ls0, inv1 = 4096.0f * kInv / ls1;

    int r0l = 16 * wid + (lane >> 2);
    size_t m0r = (size_t)b * SEQ + q0 + r0l;
    __nv_bfloat16* c0p = g_c + m0r * 1024 + h * 64;
    __nv_bfloat16* c1p = g_c + (m0r + 8) * 1024 + h * 64;
    #pragma unroll
    for (int ni = 0; ni < 8; ni++) {
        int d = 8 * ni + 2 * (lane & 3);
        float v00 = oc[ni][0] * inv0, v01 = oc[ni][1] * inv0;
        float v10 = oc[ni][2] * inv1, v11 = oc[ni][3] * inv1;
        *(uint32_t*)(c0p + d)       = pack_hi2(v00, v01);
        *(uint32_t*)(c0p + 512 + d) = pack_lo2(v00, v01);
        *(uint32_t*)(c1p + d)       = pack_hi2(v10, v11);
        *(uint32_t*)(c1p + 512 + d) = pack_lo2(v10, v11);
    }
}

// ---------------------------------------------------------------------------
extern "C" void kernel_launch(void* const* d_in, const int* in_sizes, int n_in,
                              void* d_out, int out_size)
{
    const float* x  = (const float*)d_in[0];
    const float* Wq = (const float*)d_in[1];
    const float* bq = (const float*)d_in[2];
    const float* Wk = (const float*)d_in[3];
    const float* bk = (const float*)d_in[4];
    const float* Wv = (const float*)d_in[5];
    const float* bv = (const float*)d_in[6];
    const float* Wp = (const float*)d_in[7];
    const float* bp = (const float*)d_in[8];
    float* out = (float*)d_out;

    cudaFuncSetAttribute(gemm_kernel, cudaFuncAttributeMaxDynamicSharedMemorySize, GEMM_SMEM);
    cudaFuncSetAttribute(attn_kernel, cudaFuncAttributeMaxDynamicSharedMemorySize, ATT_SMEM);

    conv_all<<<4096 + 4 * 256, 256>>>(x, Wq, Wk, Wv, Wp);

    gemm_kernel<<<dim3(12, 64), 256, GEMM_SMEM>>>(0, bq, bk, bv, nullptr);
    attn_kernel<<<dim3(16, 32), 256, ATT_SMEM>>>();
    gemm_kernel<<<dim3(4, 64), 256, GEMM_SMEM>>>(1, bp, nullptr, nullptr, out);
}

// round 9
// speedup vs baseline: 1.5146x; 1.2867x over previous
#include <cuda_runtime.h>
#include <cuda_bf16.h>
#include <cuda_fp16.h>
#include <math.h>
#include <stdint.h>

#define SEQ  2048
#define EMB  512
#define MTOT 8192

// ---- scratch: static device globals ----
__device__ __nv_bfloat16 g_x [(size_t)MTOT*1024];   // [hi|lo] along K
__device__ __nv_bfloat16 g_wq[(size_t)EMB*1024];
__device__ __nv_bfloat16 g_wk[(size_t)EMB*1024];
__device__ __nv_bfloat16 g_wv[(size_t)EMB*1024];
__device__ __nv_bfloat16 g_wp[(size_t)EMB*1024];
__device__ __half        g_qf [(size_t)32*SEQ*64];  // [bh][n][64] single fp16
__device__ __half        g_kf [(size_t)32*SEQ*64];  // [bh][n][64] single fp16
__device__ __half        g_vf [(size_t)32*SEQ*64];  // [bh][n][64] single fp16
__device__ __nv_bfloat16 g_c [(size_t)MTOT*1024];   // ctx [m][hi512|lo512]

__device__ __forceinline__ uint32_t smem_u32(const void* p) {
    uint32_t a;
    asm("{ .reg .u64 t; cvta.to.shared.u64 t, %1; cvt.u32.u64 %0, t; }" : "=r"(a) : "l"(p));
    return a;
}

#define CP16(d, s) asm volatile("cp.async.cg.shared.global [%0], [%1], 16;" :: "r"(d), "l"(s))
#define CPC()      asm volatile("cp.async.commit_group;" ::: "memory")
#define CPW1()     asm volatile("cp.async.wait_group 1;" ::: "memory")
#define CPW2()     asm volatile("cp.async.wait_group 2;" ::: "memory")

#define LDSM4(r, a) \
    asm volatile("ldmatrix.sync.aligned.m8n8.x4.shared.b16 {%0,%1,%2,%3}, [%4];" \
        : "=r"((r)[0]),"=r"((r)[1]),"=r"((r)[2]),"=r"((r)[3]) : "r"(a))
#define LDSM4T(r, a) \
    asm volatile("ldmatrix.sync.aligned.m8n8.x4.trans.shared.b16 {%0,%1,%2,%3}, [%4];" \
        : "=r"((r)[0]),"=r"((r)[1]),"=r"((r)[2]),"=r"((r)[3]) : "r"(a))

#define MMA(c, a, b0, b1) \
    asm volatile("mma.sync.aligned.m16n8k16.row.col.f32.bf16.bf16.f32 " \
        "{%0,%1,%2,%3},{%4,%5,%6,%7},{%8,%9},{%0,%1,%2,%3};" \
        : "+f"((c)[0]),"+f"((c)[1]),"+f"((c)[2]),"+f"((c)[3]) \
        : "r"((a)[0]),"r"((a)[1]),"r"((a)[2]),"r"((a)[3]),"r"(b0),"r"(b1))
#define MMAH(c, a, b0, b1) \
    asm volatile("mma.sync.aligned.m16n8k16.row.col.f32.f16.f16.f32 " \
        "{%0,%1,%2,%3},{%4,%5,%6,%7},{%8,%9},{%0,%1,%2,%3};" \
        : "+f"((c)[0]),"+f"((c)[1]),"+f"((c)[2]),"+f"((c)[3]) \
        : "r"((a)[0]),"r"((a)[1]),"r"((a)[2]),"r"((a)[3]),"r"(b0),"r"(b1))

__device__ __forceinline__ uint32_t packb(__nv_bfloat16 a, __nv_bfloat16 b) {
    return (uint32_t)__bfloat16_as_ushort(a) | ((uint32_t)__bfloat16_as_ushort(b) << 16);
}
__device__ __forceinline__ uint32_t pack_hi2(float a, float b) {
    return packb(__float2bfloat16(a), __float2bfloat16(b));
}
__device__ __forceinline__ uint32_t pack_lo2(float a, float b) {
    __nv_bfloat16 ha = __float2bfloat16(a), hb = __float2bfloat16(b);
    return packb(__float2bfloat16(a - __bfloat162float(ha)),
                 __float2bfloat16(b - __bfloat162float(hb)));
}
__device__ __forceinline__ uint32_t packh(float a, float b) {
    __half2 t = __floats2half2_rn(a, b);
    return *reinterpret_cast<uint32_t*>(&t);
}

// ---------------- fp32 -> [hi|lo] bf16, all 5 tensors in one launch ----------------
__global__ void conv_all(
    const float* __restrict__ x,  const float* __restrict__ Wq,
    const float* __restrict__ Wk, const float* __restrict__ Wv,
    const float* __restrict__ Wp)
{
    const float* src;
    __nv_bfloat16* dst;
    int bid = blockIdx.x;
    if (bid < 4096) { src = x; dst = g_x; }
    else {
        int w = (bid - 4096) >> 8;
        bid = (bid - 4096) & 255;
        switch (w) {
            case 0: src = Wq; dst = g_wq; break;
            case 1: src = Wk; dst = g_wk; break;
            case 2: src = Wv; dst = g_wv; break;
            default: src = Wp; dst = g_wp; break;
        }
    }
    int i4 = ((blockIdx.x < 4096 ? blockIdx.x : bid) * 256 + threadIdx.x) * 4;
    float4 v = *(const float4*)(src + i4);
    int m = i4 >> 9, e = i4 & 511;
    *(uint2*)(dst + (size_t)m * 1024 + e) =
        make_uint2(pack_hi2(v.x, v.y), pack_hi2(v.z, v.w));
    *(uint2*)(dst + (size_t)m * 1024 + 512 + e) =
        make_uint2(pack_lo2(v.x, v.y), pack_lo2(v.z, v.w));
}

// ---------------- GEMM: 128x128 tile, 2-term (A: hi,lo x B: hi), 16 chunks ----------------
__device__ __forceinline__ void gemm_ld_stage(
    const __nv_bfloat16* __restrict__ A, const __nv_bfloat16* __restrict__ B,
    int m0, int bn0, int chunk, uint32_t sstage, int tid)
{
    int seg = chunk >> 3, i = chunk & 7;
    int kA = ((seg == 1) ? 512 : 0) + i * 64;   // A segs: hi, lo
    int kB = i * 64;                            // B seg: hi only
    #pragma unroll
    for (int j = 0; j < 4; j++) {
        int idx = tid + j * 256;
        int r = idx >> 3, c = idx & 7;
        uint32_t off = r * 128 + ((c ^ (r & 7)) << 4);
        CP16(sstage + off,         A + (size_t)(m0 + r) * 1024 + kA + c * 8);
        CP16(sstage + 16384 + off, B + (size_t)(bn0 + r) * 1024 + kB + c * 8);
    }
}

#define GEMM_SMEM 98304

__global__ void __launch_bounds__(256, 2) gemm_kernel(
    int mode, const float* __restrict__ bq, const float* __restrict__ bk,
    const float* __restrict__ bv, float* __restrict__ out)
{
    extern __shared__ __align__(16) char sm[];
    uint32_t sb = smem_u32(sm);
    const int tid = threadIdx.x, lane = tid & 31, wid = tid >> 5;
    const int wm = wid >> 2, wn = wid & 3;
    const int m0 = blockIdx.y * 128, c0 = blockIdx.x * 128;

    const __nv_bfloat16 *A, *B;
    const float* bias;
    int w = 0, bn0 = c0;
    if (mode == 0) {
        w = c0 >> 9; bn0 = c0 & 511;
        A = g_x;
        B = (w == 0) ? g_wq : (w == 1) ? g_wk : g_wv;
        bias = (w == 0) ? bq : (w == 1) ? bk : bv;
    } else {
        A = g_c; B = g_wp; bias = bq;
    }
    const int NC = 16;

    float acc[4][4][4];
    #pragma unroll
    for (int i = 0; i < 4; i++)
        #pragma unroll
        for (int j = 0; j < 4; j++)
            #pragma unroll
            for (int k = 0; k < 4; k++) acc[i][j][k] = 0.f;

    gemm_ld_stage(A, B, m0, bn0, 0, sb, tid);          CPC();
    gemm_ld_stage(A, B, m0, bn0, 1, sb + 32768, tid);  CPC();

    for (int c = 0; c < NC; c++) {
        if (c + 2 < NC) gemm_ld_stage(A, B, m0, bn0, c + 2, sb + ((c + 2) % 3) * 32768, tid);
        CPC();
        CPW2();
        __syncthreads();
        uint32_t As = sb + (c % 3) * 32768;
        uint32_t Bs = As + 16384;
        #pragma unroll
        for (int ks = 0; ks < 4; ks++) {
            uint32_t a[4][4];
            #pragma unroll
            for (int mi = 0; mi < 4; mi++) {
                int r = wm * 64 + mi * 16 + (lane & 15);
                int c16 = 2 * ks + (lane >> 4);
                LDSM4(a[mi], As + r * 128 + ((c16 ^ (r & 7)) << 4));
            }
            uint32_t bf[2][4];
            #pragma unroll
            for (int bi = 0; bi < 2; bi++) {
                int n = wn * 32 + bi * 16 + (lane & 7) + ((lane >> 4) << 3);
                int c16 = 2 * ks + ((lane >> 3) & 1);
                LDSM4(bf[bi], Bs + n * 128 + ((c16 ^ (n & 7)) << 4));
            }
            #pragma unroll
            for (int mi = 0; mi < 4; mi++)
                #pragma unroll
                for (int ni = 0; ni < 4; ni++)
                    MMA(acc[mi][ni], a[mi], bf[ni >> 1][(ni & 1) * 2], bf[ni >> 1][(ni & 1) * 2 + 1]);
        }
        __syncthreads();
    }

    // ---- epilogue ----
    #pragma unroll
    for (int mi = 0; mi < 4; mi++) {
        #pragma unroll
        for (int ni = 0; ni < 4; ni++) {
            int r0 = m0 + wm * 64 + mi * 16 + (lane >> 2);
            int col = bn0 + wn * 32 + ni * 8 + 2 * (lane & 3);
            float v00 = acc[mi][ni][0] + bias[col];
            float v01 = acc[mi][ni][1] + bias[col + 1];
            float v10 = acc[mi][ni][2] + bias[col];
            float v11 = acc[mi][ni][3] + bias[col + 1];
            if (mode == 1) {
                *(float2*)(out + (size_t)r0 * 512 + col)       = make_float2(v00, v01);
                *(float2*)(out + (size_t)(r0 + 8) * 512 + col) = make_float2(v10, v11);
            } else {
                int h = col >> 6, d = col & 63;
                __half* dst = (w == 0) ? g_qf : (w == 1) ? g_kf : g_vf;
                #pragma unroll
                for (int rr = 0; rr < 2; rr++) {
                    int r = r0 + rr * 8;
                    float va = rr ? v10 : v00, vb = rr ? v11 : v01;
                    int bh = (r >> 11) * 8 + h;
                    int n = r & 2047;
                    size_t base = ((size_t)bh * SEQ + n) * 64 + d;
                    *(uint32_t*)(dst + base) = packh(va, vb);
                }
            }
        }
    }
}

// ---------------- attention: 256 threads, 8 warps, 2 CTAs/SM ----------------
// warp = 16 q-rows x full 128 keys (two 64-key halves)
// smem: Q 0 (16K) | stage s @ 16K + 32K*s: K 0 | V 16K
#define ATT_STAGE 32768
#define ATT_SMEM  (16384 + 2 * ATT_STAGE)

__device__ __forceinline__ void attn_ld_kv(
    const __half* __restrict__ kfb, const __half* __restrict__ vfb,
    int t, uint32_t sstage, int tid)
{
    int k0 = t * 128;
    #pragma unroll
    for (int j = 0; j < 4; j++) {
        int idx = tid + j * 256;
        int r = idx >> 3, c16 = idx & 7;
        uint32_t off = r * 128 + ((c16 ^ (r & 7)) << 4);
        CP16(sstage + off,         kfb + (size_t)(k0 + r) * 64 + c16 * 8);
        CP16(sstage + 16384 + off, vfb + (size_t)(k0 + r) * 64 + c16 * 8);
    }
}

__global__ void __launch_bounds__(256, 2) attn_kernel()
{
    extern __shared__ __align__(16) char sm[];
    uint32_t sb = smem_u32(sm);
    const int tid = threadIdx.x, lane = tid & 31, wid = tid >> 5;
    const int q0 = blockIdx.x * 128;
    const int bh = blockIdx.y, b = bh >> 3, h = bh & 7;

    const __half* qfb = g_qf + (size_t)bh * SEQ * 64;
    const __half* kfb = g_kf + (size_t)bh * SEQ * 64;
    const __half* vfb = g_vf + (size_t)bh * SEQ * 64;

    // Q -> smem, grouped with stage-0 K/V
    #pragma unroll
    for (int j = 0; j < 4; j++) {
        int idx = tid + j * 256;
        int r = idx >> 3, c16 = idx & 7;
        uint32_t off = r * 128 + ((c16 ^ (r & 7)) << 4);
        CP16(sb + off, qfb + (size_t)(q0 + r) * 64 + c16 * 8);
    }
    attn_ld_kv(kfb, vfb, 0, sb + 16384, tid);
    CPC();

    float oc[8][4];
    #pragma unroll
    for (int i = 0; i < 8; i++)
        #pragma unroll
        for (int j = 0; j < 4; j++) oc[i][j] = 0.f;
    float ls0 = 0.f, ls1 = 0.f;
    const float psc = 1.0f / 4096.0f;

    for (int t = 0; t < 16; t++) {
        if (t + 1 < 16) attn_ld_kv(kfb, vfb, t + 1, sb + 16384 + ((t + 1) & 1) * ATT_STAGE, tid);
        CPC();
        CPW1();
        __syncthreads();

        uint32_t Kbase = sb + 16384 + (t & 1) * ATT_STAGE;
        uint32_t V_s = Kbase + 16384;

        #pragma unroll
        for (int half = 0; half < 2; half++) {
            const int kb = half * 64;
            float sc[8][4];
            #pragma unroll
            for (int i = 0; i < 8; i++)
                #pragma unroll
                for (int j = 0; j < 4; j++) sc[i][j] = 0.f;

            // S (16 rows x 64 keys) = Q * K   (single fp16)
            #pragma unroll
            for (int ksx = 0; ksx < 4; ksx++) {
                uint32_t ah4[4];
                int r = 16 * wid + (lane & 15);
                int c16 = 2 * ksx + (lane >> 4);
                LDSM4(ah4, sb + r * 128 + ((c16 ^ (r & 7)) << 4));
                #pragma unroll
                for (int bi = 0; bi < 4; bi++) {
                    int n = kb + bi * 16 + (lane & 7) + ((lane >> 4) << 3);
                    int c16b = 2 * ksx + ((lane >> 3) & 1);
                    uint32_t bk4[4];
                    LDSM4(bk4, Kbase + n * 128 + ((c16b ^ (n & 7)) << 4));
                    MMAH(sc[2 * bi],     ah4, bk4[0], bk4[1]);
                    MMAH(sc[2 * bi + 1], ah4, bk4[2], bk4[3]);
                }
            }

            // softmax (no max subtraction; partial sums over this half)
            #pragma unroll
            for (int j = 0; j < 8; j++) {
                float p0 = __expf(sc[j][0]), p1 = __expf(sc[j][1]);
                float p2 = __expf(sc[j][2]), p3 = __expf(sc[j][3]);
                sc[j][0] = p0; sc[j][1] = p1; sc[j][2] = p2; sc[j][3] = p3;
                ls0 += p0 + p1; ls1 += p2 + p3;
            }

            // O += P*V over these 64 keys (single fp16 P, scaled 2^-12)
            #pragma unroll
            for (int k = 0; k < 4; k++) {
                uint32_t ah4[4];
                ah4[0] = packh(sc[2*k][0] * psc,   sc[2*k][1] * psc);
                ah4[1] = packh(sc[2*k][2] * psc,   sc[2*k][3] * psc);
                ah4[2] = packh(sc[2*k+1][0] * psc, sc[2*k+1][1] * psc);
                ah4[3] = packh(sc[2*k+1][2] * psc, sc[2*k+1][3] * psc);
                #pragma unroll
                for (int vi = 0; vi < 4; vi++) {
                    uint32_t bv4[4];
                    int row = kb + 16 * k + (lane & 15);
                    int c16 = 2 * vi + (lane >> 4);
                    LDSM4T(bv4, V_s + row * 128 + ((c16 ^ (row & 7)) << 4));
                    MMAH(oc[2*vi],   ah4, bv4[0], bv4[1]);
                    MMAH(oc[2*vi+1], ah4, bv4[2], bv4[3]);
                }
            }
        }
        __syncthreads();
    }

    // reduce partial row sums across the 4 lanes sharing a row
    ls0 += __shfl_xor_sync(0xffffffffu, ls0, 1);
    ls0 += __shfl_xor_sync(0xffffffffu, ls0, 2);
    ls1 += __shfl_xor_sync(0xffffffffu, ls1, 1);
    ls1 += __shfl_xor_sync(0xffffffffu, ls1, 2);
    const float kInv = 0.04419417382415922f;  // 1/sqrt(512)
    float inv0 = 4096.0f * kInv / ls0, inv1 = 4096.0f * kInv / ls1;

    int r0l = 16 * wid + (lane >> 2);
    size_t m0r = (size_t)b * SEQ + q0 + r0l;
    __nv_bfloat16* c0p = g_c + m0r * 1024 + h * 64;
    __nv_bfloat16* c1p = g_c + (m0r + 8) * 1024 + h * 64;
    #pragma unroll
    for (int ni = 0; ni < 8; ni++) {
        int d = 8 * ni + 2 * (lane & 3);
        float v00 = oc[ni][0] * inv0, v01 = oc[ni][1] * inv0;
        float v10 = oc[ni][2] * inv1, v11 = oc[ni][3] * inv1;
        *(uint32_t*)(c0p + d)       = pack_hi2(v00, v01);
        *(uint32_t*)(c0p + 512 + d) = pack_lo2(v00, v01);
        *(uint32_t*)(c1p + d)       = pack_hi2(v10, v11);
        *(uint32_t*)(c1p + 512 + d) = pack_lo2(v10, v11);
    }
}

// ---------------------------------------------------------------------------
extern "C" void kernel_launch(void* const* d_in, const int* in_sizes, int n_in,
                              void* d_out, int out_size)
{
    const float* x  = (const float*)d_in[0];
    const float* Wq = (const float*)d_in[1];
    const float* bq = (const float*)d_in[2];
    const float* Wk = (const float*)d_in[3];
    const float* bk = (const float*)d_in[4];
    const float* Wv = (const float*)d_in[5];
    const float* bv = (const float*)d_in[6];
    const float* Wp = (const float*)d_in[7];
    const float* bp = (const float*)d_in[8];
    float* out = (float*)d_out;

    cudaFuncSetAttribute(gemm_kernel, cudaFuncAttributeMaxDynamicSharedMemorySize, GEMM_SMEM);
    cudaFuncSetAttribute(attn_kernel, cudaFuncAttributeMaxDynamicSharedMemorySize, ATT_SMEM);

    conv_all<<<4096 + 4 * 256, 256>>>(x, Wq, Wk, Wv, Wp);

    gemm_kernel<<<dim3(12, 64), 256, GEMM_SMEM>>>(0, bq, bk, bv, nullptr);
    attn_kernel<<<dim3(16, 32), 256, ATT_SMEM>>>();
    gemm_kernel<<<dim3(4, 64), 256, GEMM_SMEM>>>(1, bp, nullptr, nullptr, out);
}

// round 11
// speedup vs baseline: 1.6801x; 1.1093x over previous
#include <cuda_runtime.h>
#include <cuda_bf16.h>
#include <cuda_fp16.h>
#include <math.h>
#include <stdint.h>

#define SEQ  2048
#define EMB  512
#define MTOT 8192

// ---- scratch: static device globals ----
__device__ __nv_bfloat16 g_x [(size_t)MTOT*1024];   // [hi|lo] along K
__device__ __nv_bfloat16 g_wq[(size_t)EMB*1024];
__device__ __nv_bfloat16 g_wk[(size_t)EMB*1024];
__device__ __nv_bfloat16 g_wv[(size_t)EMB*1024];
__device__ __nv_bfloat16 g_wp[(size_t)EMB*1024];
__device__ __half        g_qf [(size_t)32*SEQ*64];  // [bh][n][64] single fp16
__device__ __half        g_kf [(size_t)32*SEQ*64];  // [bh][n][64] single fp16
__device__ __half        g_vf [(size_t)32*SEQ*64];  // [bh][n][64] single fp16
__device__ __nv_bfloat16 g_c [(size_t)MTOT*1024];   // ctx [m][hi512|lo512]

__device__ __forceinline__ uint32_t smem_u32(const void* p) {
    uint32_t a;
    asm("{ .reg .u64 t; cvta.to.shared.u64 t, %1; cvt.u32.u64 %0, t; }" : "=r"(a) : "l"(p));
    return a;
}
__device__ __forceinline__ float ex2(float x) {
    float r;
    asm("ex2.approx.ftz.f32 %0, %1;" : "=f"(r) : "f"(x));
    return r;
}

#define CP16(d, s) asm volatile("cp.async.cg.shared.global [%0], [%1], 16;" :: "r"(d), "l"(s))
#define CPC()      asm volatile("cp.async.commit_group;" ::: "memory")
#define CPW1()     asm volatile("cp.async.wait_group 1;" ::: "memory")

#define LDSM4(r, a) \
    asm volatile("ldmatrix.sync.aligned.m8n8.x4.shared.b16 {%0,%1,%2,%3}, [%4];" \
        : "=r"((r)[0]),"=r"((r)[1]),"=r"((r)[2]),"=r"((r)[3]) : "r"(a))
#define LDSM4T(r, a) \
    asm volatile("ldmatrix.sync.aligned.m8n8.x4.trans.shared.b16 {%0,%1,%2,%3}, [%4];" \
        : "=r"((r)[0]),"=r"((r)[1]),"=r"((r)[2]),"=r"((r)[3]) : "r"(a))

#define MMA(c, a, b0, b1) \
    asm volatile("mma.sync.aligned.m16n8k16.row.col.f32.bf16.bf16.f32 " \
        "{%0,%1,%2,%3},{%4,%5,%6,%7},{%8,%9},{%0,%1,%2,%3};" \
        : "+f"((c)[0]),"+f"((c)[1]),"+f"((c)[2]),"+f"((c)[3]) \
        : "r"((a)[0]),"r"((a)[1]),"r"((a)[2]),"r"((a)[3]),"r"(b0),"r"(b1))
#define MMAH(c, a, b0, b1) \
    asm volatile("mma.sync.aligned.m16n8k16.row.col.f32.f16.f16.f32 " \
        "{%0,%1,%2,%3},{%4,%5,%6,%7},{%8,%9},{%0,%1,%2,%3};" \
        : "+f"((c)[0]),"+f"((c)[1]),"+f"((c)[2]),"+f"((c)[3]) \
        : "r"((a)[0]),"r"((a)[1]),"r"((a)[2]),"r"((a)[3]),"r"(b0),"r"(b1))

__device__ __forceinline__ uint32_t packb(__nv_bfloat16 a, __nv_bfloat16 b) {
    return (uint32_t)__bfloat16_as_ushort(a) | ((uint32_t)__bfloat16_as_ushort(b) << 16);
}
__device__ __forceinline__ uint32_t pack_hi2(float a, float b) {
    return packb(__float2bfloat16(a), __float2bfloat16(b));
}
__device__ __forceinline__ uint32_t pack_lo2(float a, float b) {
    __nv_bfloat16 ha = __float2bfloat16(a), hb = __float2bfloat16(b);
    return packb(__float2bfloat16(a - __bfloat162float(ha)),
                 __float2bfloat16(b - __bfloat162float(hb)));
}
__device__ __forceinline__ uint32_t packh(float a, float b) {
    __half2 t = __floats2half2_rn(a, b);
    return *reinterpret_cast<uint32_t*>(&t);
}

// ---------------- fp32 -> [hi|lo] bf16, all 5 tensors in one launch ----------------
__global__ void conv_all(
    const float* __restrict__ x,  const float* __restrict__ Wq,
    const float* __restrict__ Wk, const float* __restrict__ Wv,
    const float* __restrict__ Wp)
{
    const float* src;
    __nv_bfloat16* dst;
    int bid = blockIdx.x;
    if (bid < 4096) { src = x; dst = g_x; }
    else {
        int w = (bid - 4096) >> 8;
        bid = (bid - 4096) & 255;
        switch (w) {
            case 0: src = Wq; dst = g_wq; break;
            case 1: src = Wk; dst = g_wk; break;
            case 2: src = Wv; dst = g_wv; break;
            default: src = Wp; dst = g_wp; break;
        }
    }
    int i4 = ((blockIdx.x < 4096 ? blockIdx.x : bid) * 256 + threadIdx.x) * 4;
    float4 v = *(const float4*)(src + i4);
    int m = i4 >> 9, e = i4 & 511;
    *(uint2*)(dst + (size_t)m * 1024 + e) =
        make_uint2(pack_hi2(v.x, v.y), pack_hi2(v.z, v.w));
    *(uint2*)(dst + (size_t)m * 1024 + 512 + e) =
        make_uint2(pack_lo2(v.x, v.y), pack_lo2(v.z, v.w));
}

// ---------------- GEMM: 128x128 tile, double-duty chunks ----------------
// stage (48KB): Ah 0 | Al 16K | B 32K; per chunk do (Ah x B) + (Al x B)
#define GEMM_STAGE 49152
#define GEMM_SMEM  (2 * GEMM_STAGE)

__device__ __forceinline__ void gemm_ld_stage(
    const __nv_bfloat16* __restrict__ A, const __nv_bfloat16* __restrict__ B,
    int m0, int bn0, int chunk, uint32_t sstage, int tid)
{
    int kA = chunk * 64;
    #pragma unroll
    for (int j = 0; j < 4; j++) {
        int idx = tid + j * 256;
        int r = idx >> 3, c = idx & 7;
        uint32_t off = r * 128 + ((c ^ (r & 7)) << 4);
        CP16(sstage + off,         A + (size_t)(m0 + r) * 1024 + kA + c * 8);
        CP16(sstage + 16384 + off, A + (size_t)(m0 + r) * 1024 + 512 + kA + c * 8);
        CP16(sstage + 32768 + off, B + (size_t)(bn0 + r) * 1024 + kA + c * 8);
    }
}

__global__ void __launch_bounds__(256, 2) gemm_kernel(
    int mode, const float* __restrict__ bq, const float* __restrict__ bk,
    const float* __restrict__ bv, float* __restrict__ out)
{
    extern __shared__ __align__(16) char sm[];
    uint32_t sb = smem_u32(sm);
    const int tid = threadIdx.x, lane = tid & 31, wid = tid >> 5;
    const int wm = wid >> 2, wn = wid & 3;
    const int m0 = blockIdx.y * 128, c0 = blockIdx.x * 128;

    const __nv_bfloat16 *A, *B;
    const float* bias;
    int w = 0, bn0 = c0;
    if (mode == 0) {
        w = c0 >> 9; bn0 = c0 & 511;
        A = g_x;
        B = (w == 0) ? g_wq : (w == 1) ? g_wk : g_wv;
        bias = (w == 0) ? bq : (w == 1) ? bk : bv;
    } else {
        A = g_c; B = g_wp; bias = bq;
    }

    float acc[4][4][4];
    #pragma unroll
    for (int i = 0; i < 4; i++)
        #pragma unroll
        for (int j = 0; j < 4; j++)
            #pragma unroll
            for (int k = 0; k < 4; k++) acc[i][j][k] = 0.f;

    gemm_ld_stage(A, B, m0, bn0, 0, sb, tid);              CPC();
    gemm_ld_stage(A, B, m0, bn0, 1, sb + GEMM_STAGE, tid); CPC();

    for (int c = 0; c < 8; c++) {
        CPW1();
        __syncthreads();
        uint32_t As = sb + (c & 1) * GEMM_STAGE;
        uint32_t Bs = As + 32768;
        #pragma unroll
        for (int ks = 0; ks < 4; ks++) {
            uint32_t bf[2][4];
            #pragma unroll
            for (int bi = 0; bi < 2; bi++) {
                int n = wn * 32 + bi * 16 + (lane & 7) + ((lane >> 4) << 3);
                int c16 = 2 * ks + ((lane >> 3) & 1);
                LDSM4(bf[bi], Bs + n * 128 + ((c16 ^ (n & 7)) << 4));
            }
            #pragma unroll
            for (int term = 0; term < 2; term++) {
                uint32_t a[4][4];
                uint32_t Ab = As + term * 16384;
                #pragma unroll
                for (int mi = 0; mi < 4; mi++) {
                    int r = wm * 64 + mi * 16 + (lane & 15);
                    int c16 = 2 * ks + (lane >> 4);
                    LDSM4(a[mi], Ab + r * 128 + ((c16 ^ (r & 7)) << 4));
                }
                #pragma unroll
                for (int mi = 0; mi < 4; mi++)
                    #pragma unroll
                    for (int ni = 0; ni < 4; ni++)
                        MMA(acc[mi][ni], a[mi], bf[ni >> 1][(ni & 1) * 2], bf[ni >> 1][(ni & 1) * 2 + 1]);
            }
        }
        __syncthreads();
        if (c + 2 < 8) {
            gemm_ld_stage(A, B, m0, bn0, c + 2, sb + (c & 1) * GEMM_STAGE, tid);
            CPC();
        }
    }

    // ---- epilogue ----
    #pragma unroll
    for (int mi = 0; mi < 4; mi++) {
        #pragma unroll
        for (int ni = 0; ni < 4; ni++) {
            int r0 = m0 + wm * 64 + mi * 16 + (lane >> 2);
            int col = bn0 + wn * 32 + ni * 8 + 2 * (lane & 3);
            float v00 = acc[mi][ni][0] + bias[col];
            float v01 = acc[mi][ni][1] + bias[col + 1];
            float v10 = acc[mi][ni][2] + bias[col];
            float v11 = acc[mi][ni][3] + bias[col + 1];
            if (mode == 1) {
                *(float2*)(out + (size_t)r0 * 512 + col)       = make_float2(v00, v01);
                *(float2*)(out + (size_t)(r0 + 8) * 512 + col) = make_float2(v10, v11);
            } else {
                int h = col >> 6, d = col & 63;
                __half* dst = (w == 0) ? g_qf : (w == 1) ? g_kf : g_vf;
                #pragma unroll
                for (int rr = 0; rr < 2; rr++) {
                    int r = r0 + rr * 8;
                    float va = rr ? v10 : v00, vb = rr ? v11 : v01;
                    int bh = (r >> 11) * 8 + h;
                    int n = r & 2047;
                    size_t base = ((size_t)bh * SEQ + n) * 64 + d;
                    *(uint32_t*)(dst + base) = packh(va, vb);
                }
            }
        }
    }
}

// ---------------- attention: 256 threads, 8 warps, 2 CTAs/SM ----------------
// warp = 16 q-rows x full 128 keys (two 64-key halves); Q frags hoisted.
// smem: Q 0 (16K) | stage s @ 16K + 32K*s: K 0 | V 16K
#define ATT_STAGE 32768
#define ATT_SMEM  (16384 + 2 * ATT_STAGE)

__device__ __forceinline__ void attn_ld_kv(
    const __half* __restrict__ kfb, const __half* __restrict__ vfb,
    int t, uint32_t sstage, int tid)
{
    int k0 = t * 128;
    #pragma unroll
    for (int j = 0; j < 4; j++) {
        int idx = tid + j * 256;
        int r = idx >> 3, c16 = idx & 7;
        uint32_t off = r * 128 + ((c16 ^ (r & 7)) << 4);
        CP16(sstage + off,         kfb + (size_t)(k0 + r) * 64 + c16 * 8);
        CP16(sstage + 16384 + off, vfb + (size_t)(k0 + r) * 64 + c16 * 8);
    }
}

__global__ void __launch_bounds__(256, 2) attn_kernel()
{
    extern __shared__ __align__(16) char sm[];
    uint32_t sb = smem_u32(sm);
    const int tid = threadIdx.x, lane = tid & 31, wid = tid >> 5;
    const int q0 = blockIdx.x * 128;
    const int bh = blockIdx.y, b = bh >> 3, h = bh & 7;

    const __half* qfb = g_qf + (size_t)bh * SEQ * 64;
    const __half* kfb = g_kf + (size_t)bh * SEQ * 64;
    const __half* vfb = g_vf + (size_t)bh * SEQ * 64;

    // Q -> smem (group 0), stage-0 K/V (group 1)
    #pragma unroll
    for (int j = 0; j < 4; j++) {
        int idx = tid + j * 256;
        int r = idx >> 3, c16 = idx & 7;
        uint32_t off = r * 128 + ((c16 ^ (r & 7)) << 4);
        CP16(sb + off, qfb + (size_t)(q0 + r) * 64 + c16 * 8);
    }
    CPC();
    attn_ld_kv(kfb, vfb, 0, sb + 16384, tid);
    CPC();

    // Q frags hoisted: constant across all 16 tiles
    CPW1();                 // group 0 (Q) complete
    __syncthreads();
    uint32_t qf4[4][4];
    #pragma unroll
    for (int ksx = 0; ksx < 4; ksx++) {
        int r = 16 * wid + (lane & 15);
        int c16 = 2 * ksx + (lane >> 4);
        LDSM4(qf4[ksx], sb + r * 128 + ((c16 ^ (r & 7)) << 4));
    }

    float oc[8][4];
    #pragma unroll
    for (int i = 0; i < 8; i++)
        #pragma unroll
        for (int j = 0; j < 4; j++) oc[i][j] = 0.f;
    float ls0 = 0.f, ls1 = 0.f;
    const float kLog2e = 1.44269504088896f;

    for (int t = 0; t < 16; t++) {
        if (t + 1 < 16) attn_ld_kv(kfb, vfb, t + 1, sb + 16384 + ((t + 1) & 1) * ATT_STAGE, tid);
        CPC();
        CPW1();
        __syncthreads();

        uint32_t Kbase = sb + 16384 + (t & 1) * ATT_STAGE;
        uint32_t V_s = Kbase + 16384;

        #pragma unroll
        for (int half = 0; half < 2; half++) {
            const int kb = half * 64;
            float sc[8][4];
            #pragma unroll
            for (int i = 0; i < 8; i++)
                #pragma unroll
                for (int j = 0; j < 4; j++) sc[i][j] = 0.f;

            // S (16 rows x 64 keys) = Q * K   (single fp16; Q frags in regs)
            #pragma unroll
            for (int ksx = 0; ksx < 4; ksx++) {
                #pragma unroll
                for (int bi = 0; bi < 4; bi++) {
                    int n = kb + bi * 16 + (lane & 7) + ((lane >> 4) << 3);
                    int c16b = 2 * ksx + ((lane >> 3) & 1);
                    uint32_t bk4[4];
                    LDSM4(bk4, Kbase + n * 128 + ((c16b ^ (n & 7)) << 4));
                    MMAH(sc[2 * bi],     qf4[ksx], bk4[0], bk4[1]);
                    MMAH(sc[2 * bi + 1], qf4[ksx], bk4[2], bk4[3]);
                }
            }

            // softmax: p_scaled = ex2(s*log2e - 12) == exp(s) * 2^-12 (exact pow2)
            #pragma unroll
            for (int j = 0; j < 8; j++) {
                float p0 = ex2(fmaf(sc[j][0], kLog2e, -12.f));
                float p1 = ex2(fmaf(sc[j][1], kLog2e, -12.f));
                float p2 = ex2(fmaf(sc[j][2], kLog2e, -12.f));
                float p3 = ex2(fmaf(sc[j][3], kLog2e, -12.f));
                sc[j][0] = p0; sc[j][1] = p1; sc[j][2] = p2; sc[j][3] = p3;
                ls0 += p0 + p1; ls1 += p2 + p3;
            }

            // O += P*V over these 64 keys
            #pragma unroll
            for (int k = 0; k < 4; k++) {
                uint32_t ah4[4];
                ah4[0] = packh(sc[2*k][0],   sc[2*k][1]);
                ah4[1] = packh(sc[2*k][2],   sc[2*k][3]);
                ah4[2] = packh(sc[2*k+1][0], sc[2*k+1][1]);
                ah4[3] = packh(sc[2*k+1][2], sc[2*k+1][3]);
                #pragma unroll
                for (int vi = 0; vi < 4; vi++) {
                    uint32_t bv4[4];
                    int row = kb + 16 * k + (lane & 15);
                    int c16 = 2 * vi + (lane >> 4);
                    LDSM4T(bv4, V_s + row * 128 + ((c16 ^ (row & 7)) << 4));
                    MMAH(oc[2*vi],   ah4, bv4[0], bv4[1]);
                    MMAH(oc[2*vi+1], ah4, bv4[2], bv4[3]);
                }
            }
        }
        __syncthreads();
    }

    // reduce partial row sums across the 4 lanes sharing a row
    ls0 += __shfl_xor_sync(0xffffffffu, ls0, 1);
    ls0 += __shfl_xor_sync(0xffffffffu, ls0, 2);
    ls1 += __shfl_xor_sync(0xffffffffu, ls1, 1);
    ls1 += __shfl_xor_sync(0xffffffffu, ls1, 2);
    const float kInv = 0.04419417382415922f;  // 1/sqrt(512)
    float inv0 = kInv / ls0, inv1 = kInv / ls1;

    int r0l = 16 * wid + (lane >> 2);
    size_t m0r = (size_t)b * SEQ + q0 + r0l;
    __nv_bfloat16* c0p = g_c + m0r * 1024 + h * 64;
    __nv_bfloat16* c1p = g_c + (m0r + 8) * 1024 + h * 64;
    #pragma unroll
    for (int ni = 0; ni < 8; ni++) {
        int d = 8 * ni + 2 * (lane & 3);
        float v00 = oc[ni][0] * inv0, v01 = oc[ni][1] * inv0;
        float v10 = oc[ni][2] * inv1, v11 = oc[ni][3] * inv1;
        *(uint32_t*)(c0p + d)       = pack_hi2(v00, v01);
        *(uint32_t*)(c0p + 512 + d) = pack_lo2(v00, v01);
        *(uint32_t*)(c1p + d)       = pack_hi2(v10, v11);
        *(uint32_t*)(c1p + 512 + d) = pack_lo2(v10, v11);
    }
}

// ---------------------------------------------------------------------------
extern "C" void kernel_launch(void* const* d_in, const int* in_sizes, int n_in,
                              void* d_out, int out_size)
{
    const float* x  = (const float*)d_in[0];
    const float* Wq = (const float*)d_in[1];
    const float* bq = (const float*)d_in[2];
    const float* Wk = (const float*)d_in[3];
    const float* bk = (const float*)d_in[4];
    const float* Wv = (const float*)d_in[5];
    const float* bv = (const float*)d_in[6];
    const float* Wp = (const float*)d_in[7];
    const float* bp = (const float*)d_in[8];
    float* out = (float*)d_out;

    cudaFuncSetAttribute(gemm_kernel, cudaFuncAttributeMaxDynamicSharedMemorySize, GEMM_SMEM);
    cudaFuncSetAttribute(attn_kernel, cudaFuncAttributeMaxDynamicSharedMemorySize, ATT_SMEM);

    conv_all<<<4096 + 4 * 256, 256>>>(x, Wq, Wk, Wv, Wp);

    gemm_kernel<<<dim3(12, 64), 256, GEMM_SMEM>>>(0, bq, bk, bv, nullptr);
    attn_kernel<<<dim3(16, 32), 256, ATT_SMEM>>>();
    gemm_kernel<<<dim3(4, 64), 256, GEMM_SMEM>>>(1, bp, nullptr, nullptr, out);
}